// round 12
// baseline (speedup 1.0000x reference)
#include <cuda_runtime.h>
#include <cuda_fp16.h>
#include <math_constants.h>
#include <cstdint>

#define Bn 128
#define Hn 128

__device__ float    g_scores[Bn * Bn];
__device__ unsigned g_cnt = 0;
// Pre-converted, pre-swizzled fp16 tiles (tile = 128 rows x 256B swizzled)
__device__ __align__(16) char g_Qh[32 * 32768];    // 1MB: 32 mi-tiles
__device__ __align__(16) char g_Ph[128 * 32768];   // 4MB: 128 c-tiles
// Deferred per-warp row-max scratch: [cta][c][wn][64]
__device__ __align__(16) float g_rmax[256 * 32 * 2 * 64];

// smem layout: mbarriers | A (16KB) | B bufs (3 x 32KB)
#define MB_FULL(b)  ((b) * 8)           // 0, 8, 16
#define MB_EMPTY(b) (24 + (b) * 8)      // 24, 32, 40
#define A_OFF       128
#define B_OFF(b)    (16640 + (b) * 32768)
#define SMEM_BYTES  (16640 + 3 * 32768) // 114944 (2 CTAs/SM fits 228KB)

__device__ __forceinline__ uint32_t smem_u32(const void* p) {
    uint32_t a;
    asm("{ .reg .u64 t; cvta.to.shared.u64 t, %1; cvt.u32.u64 %0, t; }" : "=r"(a) : "l"(p));
    return a;
}
__device__ __forceinline__ void cp16(uint32_t sm, const void* g) {
    asm volatile("cp.async.cg.shared.global [%0], [%1], 16;" :: "r"(sm), "l"(g));
}
#define MBAR_INIT(mb, cnt) \
    asm volatile("mbarrier.init.shared.b64 [%0], %1;" :: "r"((uint32_t)(mb)), "r"((uint32_t)(cnt)) : "memory")
#define MBAR_ARRIVE(mb) \
    asm volatile("{ .reg .b64 s; mbarrier.arrive.shared.b64 s, [%0]; }" :: "r"((uint32_t)(mb)) : "memory")
#define CPASYNC_ARRIVE_NOINC(mb) \
    asm volatile("cp.async.mbarrier.arrive.noinc.shared.b64 [%0];" :: "r"((uint32_t)(mb)) : "memory")
#define MBAR_WAIT(mb, ph) do { \
    uint32_t _m = (uint32_t)(mb); uint32_t _p = (uint32_t)(ph); uint32_t _d; \
    asm volatile("{\n\t.reg .pred p;\n\tmbarrier.try_wait.parity.shared.b64 p, [%1], %2;\n\tselp.b32 %0, 1, 0, p;\n\t}" \
                 : "=r"(_d) : "r"(_m), "r"(_p) : "memory"); \
    if (!_d) { \
        asm volatile("{\n\t.reg .pred P1;\n\tWL%=:\n\tmbarrier.try_wait.parity.shared.b64 P1, [%0], %1;\n\t@P1 bra.uni WD%=;\n\tbra.uni WL%=;\n\tWD%=:\n\t}" \
                     :: "r"(_m), "r"(_p) : "memory"); \
    } } while (0)

__device__ __forceinline__ void ldsm4(uint32_t& r0, uint32_t& r1, uint32_t& r2, uint32_t& r3,
                                      uint32_t addr) {
    asm volatile("ldmatrix.sync.aligned.m8n8.x4.shared.b16 {%0,%1,%2,%3}, [%4];"
                 : "=r"(r0), "=r"(r1), "=r"(r2), "=r"(r3) : "r"(addr));
}
__device__ __forceinline__ void mma16h(uint32_t* d, const uint32_t* a, uint32_t b0, uint32_t b1) {
    asm volatile(
        "mma.sync.aligned.m16n8k16.row.col.f16.f16.f16.f16 "
        "{%0,%1}, {%2,%3,%4,%5}, {%6,%7}, {%0,%1};"
        : "+r"(d[0]), "+r"(d[1])
        : "r"(a[0]), "r"(a[1]), "r"(a[2]), "r"(a[3]), "r"(b0), "r"(b1));
}
__device__ __forceinline__ uint32_t hmax2(uint32_t a, uint32_t b) {
    uint32_t r; asm("max.f16x2 %0, %1, %2;" : "=r"(r) : "r"(a), "r"(b)); return r;
}
__device__ __forceinline__ float hpair_max_f32(uint32_t p) {
    __half2 h = *reinterpret_cast<__half2*>(&p);
    return fmaxf(__half2float(__low2half(h)), __half2float(__high2half(h)));
}

// ---------------------------------------------------------------------------
// Pre-kernel: fp32 [128 x 128] tile -> fp16 swizzled (row*256B, unit^(row&7)).
// ---------------------------------------------------------------------------
extern "C" __global__ void __launch_bounds__(256)
colbert_convert(const float* __restrict__ Q, const float* __restrict__ P)
{
    const int bid = blockIdx.x, t = threadIdx.x;
    const float4* src;
    char* dst;
    if (bid < 128) { src = reinterpret_cast<const float4*>(P) + (size_t)bid * 4096; dst = g_Ph + (size_t)bid * 32768; }
    else           { src = reinterpret_cast<const float4*>(Q) + (size_t)(bid - 128) * 4096; dst = g_Qh + (size_t)(bid - 128) * 32768; }
    #pragma unroll
    for (int j = 0; j < 16; ++j) {
        int f4 = j * 256 + t;
        float4 v = src[f4];
        int row = f4 >> 5, c4 = f4 & 31;
        __half2 h0 = __floats2half2_rn(v.x, v.y);
        __half2 h1 = __floats2half2_rn(v.z, v.w);
        uint2 w;
        w.x = *reinterpret_cast<uint32_t*>(&h0);
        w.y = *reinterpret_cast<uint32_t*>(&h1);
        int off = row * 256 + ((((c4 >> 1) ^ (row & 7))) << 4) + ((c4 & 1) << 3);
        *reinterpret_cast<uint2*>(dst + off) = w;
    }
}

// ---------------------------------------------------------------------------
// Main: 256 CTAs x 128 threads, 2 CTAs/SM. CTA (mi2=bid>>2: rows [mi2*64,+64),
// cg=bid&3). Warps: wm=wid>>1 (M=32 = one b), wn=wid&1 (N=64 half).
// mbarrier producer/consumer ring over 3 B buffers; NO __syncthreads in loop.
// ---------------------------------------------------------------------------
extern "C" __global__ void __launch_bounds__(128, 2)
colbert_fused(float* __restrict__ out)
{
    extern __shared__ __align__(128) char smem[];
    const uint32_t sbase = smem_u32(smem);

    const int t    = threadIdx.x;
    const int lane = t & 31;
    const int wid  = t >> 5;
    const int wm   = wid >> 1;
    const int wn   = wid & 1;
    const int mi2  = blockIdx.x >> 2;
    const int cg   = blockIdx.x & 3;
    const int gid  = lane >> 2;
    const int tig  = lane & 3;

    // ---- init mbarriers
    if (t == 0) {
        #pragma unroll
        for (int b = 0; b < 3; ++b) {
            MBAR_INIT(sbase + MB_FULL(b), 128);  // cp.async noinc arrives
            MBAR_INIT(sbase + MB_EMPTY(b), 4);   // one arrive per warp
        }
    }
    __syncthreads();

    // ---- prologue: A first, then tiles 0..2 with full-mbar arrives
    const char* gB0 = g_Ph + (size_t)(cg * 32) * 32768;
    {
        const char* gA = g_Qh + (size_t)(mi2 >> 1) * 32768 + (size_t)(mi2 & 1) * 16384;
        #pragma unroll
        for (int j = 0; j < 8; ++j) {
            int off = j * 2048 + t * 16;
            cp16(sbase + A_OFF + off, gA + off);
        }
        #pragma unroll
        for (int b = 0; b < 3; ++b) {
            // producer phase=1 on fresh barrier passes immediately
            MBAR_WAIT(sbase + MB_EMPTY(b), 1);
            const char* gB = gB0 + (size_t)b * 32768;
            #pragma unroll
            for (int j = 0; j < 16; ++j) {
                int off = j * 2048 + t * 16;
                cp16(sbase + B_OFF(b) + off, gB + off);
            }
            CPASYNC_ARRIVE_NOINC(sbase + MB_FULL(b));
        }
    }
    int prod_stage = 0, prod_phase = 0;   // after 3 fills: stage 0, phase flipped 1->0
    int cons_stage = 0, cons_phase = 0;

    // ---- A fragments -> registers (full[0] completion implies A landed:
    //      each thread issued A before tile0, and noinc waits on ALL prior)
    MBAR_WAIT(sbase + MB_FULL(0), 0);
    uint32_t aF[2][8][4];
    {
        const int rA = wm * 32 + (lane & 15);
        const int kqA = lane >> 4;
        #pragma unroll
        for (int mt = 0; mt < 2; ++mt) {
            const int row = rA + mt * 16;
            const uint32_t rowbase = sbase + A_OFF + row * 256;
            #pragma unroll
            for (int ks = 0; ks < 8; ++ks) {
                uint32_t addr = rowbase + (((2 * ks + kqA) ^ (row & 7)) << 4);
                ldsm4(aF[mt][ks][0], aF[mt][ks][1], aF[mt][ks][2], aF[mt][ks][3], addr);
            }
        }
    }

    const int rBl = (lane & 7) + ((lane >> 4) << 3);
    const int kqB = (lane >> 3) & 1;
    int rOff[4], rSw[4];
    #pragma unroll
    for (int np = 0; np < 4; ++np) {
        int row = wn * 64 + np * 16 + rBl;
        rOff[np] = row * 256;
        rSw[np]  = row & 7;
    }

    for (int i = 0; i < 32; ++i) {
        const int buf = cons_stage;
        const uint32_t Bbase = sbase + B_OFF(buf);
        MBAR_WAIT(sbase + MB_FULL(buf), cons_phase);
        if (++cons_stage == 3) { cons_stage = 0; cons_phase ^= 1; }

        uint32_t bF[2][4][4];
        #pragma unroll
        for (int np = 0; np < 4; ++np) {
            uint32_t addr = Bbase + rOff[np] + ((kqB ^ rSw[np]) << 4);
            ldsm4(bF[0][np][0], bF[0][np][1], bF[0][np][2], bF[0][np][3], addr);
        }

        uint32_t acc[2][8][2];   // f16x2 accumulators
        #pragma unroll
        for (int mt = 0; mt < 2; ++mt)
            #pragma unroll
            for (int nt = 0; nt < 8; ++nt) { acc[mt][nt][0] = 0u; acc[mt][nt][1] = 0u; }

        #pragma unroll
        for (int ks = 0; ks < 8; ++ks) {
            const int cur = ks & 1, nxt = cur ^ 1;
            if (ks < 7) {
                const int ku = 2 * (ks + 1) + kqB;
                #pragma unroll
                for (int np = 0; np < 4; ++np) {
                    uint32_t addr = Bbase + rOff[np] + ((ku ^ rSw[np]) << 4);
                    ldsm4(bF[nxt][np][0], bF[nxt][np][1], bF[nxt][np][2], bF[nxt][np][3], addr);
                }
            }
            #pragma unroll
            for (int np = 0; np < 4; ++np)
                #pragma unroll
                for (int mt = 0; mt < 2; ++mt) {
                    mma16h(acc[mt][2 * np],     aF[mt][ks], bF[cur][np][0], bF[cur][np][1]);
                    mma16h(acc[mt][2 * np + 1], aF[mt][ks], bF[cur][np][2], bF[cur][np][3]);
                }
        }

        // this warp is done reading buf
        if (lane == 0) MBAR_ARRIVE(sbase + MB_EMPTY(buf));

        // ---- epilogue: packed f16 row-max over 64 n-cols -> global scratch
        float* gr = g_rmax + ((size_t)(blockIdx.x * 32 + i) * 2 + wn) * 64;
        #pragma unroll
        for (int mt = 0; mt < 2; ++mt) {
            uint32_t p0 = acc[mt][0][0], p1 = acc[mt][0][1];
            #pragma unroll
            for (int nt = 1; nt < 8; ++nt) {
                p0 = hmax2(p0, acc[mt][nt][0]);
                p1 = hmax2(p1, acc[mt][nt][1]);
            }
            float m0 = hpair_max_f32(p0);
            float m1 = hpair_max_f32(p1);
            m0 = fmaxf(m0, __shfl_xor_sync(0xffffffffu, m0, 1));
            m0 = fmaxf(m0, __shfl_xor_sync(0xffffffffu, m0, 2));
            m1 = fmaxf(m1, __shfl_xor_sync(0xffffffffu, m1, 1));
            m1 = fmaxf(m1, __shfl_xor_sync(0xffffffffu, m1, 2));
            if (tig == 0) {
                gr[wm * 32 + mt * 16 + gid]     = m0;
                gr[wm * 32 + mt * 16 + 8 + gid] = m1;
            }
        }

        // ---- producer duty: fill tile i+3 into the buffer just freed
        if (i + 3 < 32) {
            const int pb = prod_stage;
            MBAR_WAIT(sbase + MB_EMPTY(pb), prod_phase);
            const char* gB = gB0 + (size_t)(i + 3) * 32768;
            #pragma unroll
            for (int j = 0; j < 16; ++j) {
                int off = j * 2048 + t * 16;
                cp16(sbase + B_OFF(pb) + off, gB + off);
            }
            CPASYNC_ARRIVE_NOINC(sbase + MB_FULL(pb));
            if (++prod_stage == 3) { prod_stage = 0; prod_phase ^= 1; }
        }
    }

    __syncthreads();  // all warps done; g_rmax visible CTA-wide

    // ---- combine: warp w handles 8 c's; lane = s-row within each b
    {
        const int b0 = mi2 * 2, b1 = mi2 * 2 + 1;
        #pragma unroll
        for (int cl = 0; cl < 8; ++cl) {
            const int ci = wid * 8 + cl;
            const float* r = g_rmax + (size_t)(blockIdx.x * 32 + ci) * 128;
            float v0 = fmaxf(r[lane],      r[64 + lane]);
            float v1 = fmaxf(r[32 + lane], r[96 + lane]);
            #pragma unroll
            for (int off = 16; off; off >>= 1) {
                v0 += __shfl_xor_sync(0xffffffffu, v0, off);
                v1 += __shfl_xor_sync(0xffffffffu, v1, off);
            }
            if (lane == 0) {
                const int c = cg * 32 + ci;
                g_scores[b0 * Bn + c] = v0;
                g_scores[b1 * Bn + c] = v1;
            }
        }
    }

    // ---- last CTA computes the loss
    __syncthreads();
    __threadfence();
    __shared__ unsigned s_rank;
    __shared__ float sred[32];
    if (t == 0) s_rank = atomicAdd(&g_cnt, 1);
    __syncthreads();
    if (s_rank != 255) return;
    if (t == 0) atomicExch(&g_cnt, 0);
    __threadfence();

    const float4* rp = reinterpret_cast<const float4*>(&g_scores[t * Bn]);
    float m = -CUDART_INF_F, diag = 0.0f;
    #pragma unroll
    for (int k4 = 0; k4 < 32; ++k4) {
        float4 v = rp[k4];
        m = fmaxf(m, fmaxf(fmaxf(v.x, v.y), fmaxf(v.z, v.w)));
        int cb = k4 * 4;
        if (t == cb + 0) diag = v.x;
        if (t == cb + 1) diag = v.y;
        if (t == cb + 2) diag = v.z;
        if (t == cb + 3) diag = v.w;
    }
    float s = 0.0f;
    #pragma unroll
    for (int k4 = 0; k4 < 32; ++k4) {
        float4 v = rp[k4];
        s += expf(50.0f * (v.x - m)) + expf(50.0f * (v.y - m)) +
             expf(50.0f * (v.z - m)) + expf(50.0f * (v.w - m));
    }
    float term = 50.0f * diag - (50.0f * m + logf(s));

    #pragma unroll
    for (int off = 16; off; off >>= 1) term += __shfl_xor_sync(0xffffffffu, term, off);
    if (lane == 0) sred[wid] = term;
    __syncthreads();
    if (t == 0) out[0] = -(sred[0] + sred[1] + sred[2] + sred[3]) / 128.0f;
}

// ---------------------------------------------------------------------------
extern "C" void kernel_launch(void* const* d_in, const int* in_sizes, int n_in,
                              void* d_out, int out_size)
{
    const float* Q = (const float*)d_in[0];  // [128, 32, 128]
    const float* P = (const float*)d_in[1];  // [128, 128, 128]
    float* out = (float*)d_out;

    cudaFuncSetAttribute(colbert_fused,
                         cudaFuncAttributeMaxDynamicSharedMemorySize, SMEM_BYTES);
    colbert_convert<<<160, 256>>>(Q, P);
    colbert_fused<<<256, 128, SMEM_BYTES>>>(out);
}